// round 8
// baseline (speedup 1.0000x reference)
#include <cuda_runtime.h>
#include <cuda_bf16.h>
#include <cstdint>

// Problem constants
#define BB    2048     // batch
#define KHIST 200      // history length
#define DD    512      // latent dim
#define HHID  1024     // 2*D
#define CBK   2048     // codebook size
#define BD    (BB*DD)  // 1048576
#define NBW   64       // CBK / 32 argmin partial chunks per row

// ---------------- scratch (device globals; no allocation allowed) ----------
__device__ float        g_u[BB * DD];
__device__ float        g_cnorm[CBK];
__device__ float        g_pval[BB * NBW];
__device__ int          g_pidx[BB * NBW];
__device__ float        g_bsum[BB];

// DAG scheduling state (zero-init; reset by reset_kernel each call)
__device__ int t_q1, t_q2, t_q3, t_q4, t_q5;
__device__ int c_w1, c_w2, c_cb;
__device__ int c_mean[16], c_hid[16], c_u[16], c_p[16];
__device__ int g_count;

// bf16 hi/lo split operands
__device__ __nv_bfloat16 g_meanH[BB * DD],   g_meanL[BB * DD];
__device__ __nv_bfloat16 g_hidH [BB * HHID], g_hidL [BB * HHID];
__device__ __nv_bfloat16 g_uH   [BB * DD],   g_uL   [BB * DD];
__device__ __nv_bfloat16 g_W1tH [HHID * DD], g_W1tL [HHID * DD];
__device__ __nv_bfloat16 g_W2tH [DD * HHID], g_W2tL [DD * HHID];
__device__ __nv_bfloat16 g_cbH  [CBK * DD],  g_cbL  [CBK * DD];

// ---------------------------------------------------------------------------
// Portable PTX helpers
// ---------------------------------------------------------------------------
__device__ __forceinline__ uint32_t smem_u32(const void* p) {
    uint32_t a;
    asm("{ .reg .u64 t; cvta.to.shared.u64 t, %1; cvt.u32.u64 %0, t; }" : "=r"(a) : "l"(p));
    return a;
}

#define CP_ASYNC16(dst, src) \
    asm volatile("cp.async.cg.shared.global [%0], [%1], 16;" :: "r"(dst), "l"(src))
#define CP_COMMIT() asm volatile("cp.async.commit_group;" ::: "memory")
#define CP_WAIT0()  asm volatile("cp.async.wait_group 0;" ::: "memory")
#define CP_WAIT1()  asm volatile("cp.async.wait_group 1;" ::: "memory")

__device__ __forceinline__ void ldsm4(uint32_t (&r)[4], uint32_t addr) {
    asm volatile("ldmatrix.sync.aligned.m8n8.x4.shared.b16 {%0,%1,%2,%3}, [%4];"
                 : "=r"(r[0]), "=r"(r[1]), "=r"(r[2]), "=r"(r[3]) : "r"(addr));
}

__device__ __forceinline__ void mma16816(float (&d)[4], const uint32_t (&a)[4],
                                         uint32_t b0, uint32_t b1) {
    asm volatile(
        "mma.sync.aligned.m16n8k16.row.col.f32.bf16.bf16.f32 "
        "{%0,%1,%2,%3}, {%4,%5,%6,%7}, {%8,%9}, {%0,%1,%2,%3};"
        : "+f"(d[0]), "+f"(d[1]), "+f"(d[2]), "+f"(d[3])
        : "r"(a[0]), "r"(a[1]), "r"(a[2]), "r"(a[3]), "r"(b0), "r"(b1));
}

__device__ __forceinline__ void split_bf16(float v, __nv_bfloat16& h, __nv_bfloat16& l) {
    h = __float2bfloat16(v);
    l = __float2bfloat16(v - __bfloat162float(h));
}

__device__ __forceinline__ int ld_acq(const int* p) {
    int v;
    asm volatile("ld.acquire.gpu.b32 %0, [%1];" : "=r"(v) : "l"(p) : "memory");
    return v;
}
__device__ __forceinline__ void wait_ge(const int* p, int tgt) {
    while (ld_acq(p) < tgt) __nanosleep(64);
}

// ---------------------------------------------------------------------------
// Q1 unit bodies (256 threads each)
// ---------------------------------------------------------------------------
// gather+mean for rows {2g, 2g+1}
__device__ void unit_gather(int g, const int* __restrict__ items,
                            const float* __restrict__ item_embed)
{
    __shared__ int sidx[2][KHIST];
    int t = threadIdx.x;
    int half = t >> 7, tt = t & 127;
    int b = 2 * g + half;
    for (int i = tt; i < KHIST; i += 128) sidx[half][i] = items[b * KHIST + i];
    __syncthreads();

    const float4* E4 = (const float4*)item_embed;
    float4 acc = make_float4(0.f, 0.f, 0.f, 0.f);
    int cnt = 0;
    #pragma unroll 4
    for (int k = 0; k < KHIST; k++) {
        int idx = sidx[half][k];
        float m = (idx != 0) ? 1.0f : 0.0f;
        cnt += (idx != 0);
        float4 v = E4[(size_t)idx * 128 + tt];
        acc.x += m * v.x; acc.y += m * v.y; acc.z += m * v.z; acc.w += m * v.w;
    }
    float inv = 1.0f / (float)cnt;
    float vals[4] = {acc.x * inv, acc.y * inv, acc.z * inv, acc.w * inv};
    size_t base = (size_t)b * DD + tt * 4;
    __nv_bfloat16 h[4], l[4];
    #pragma unroll
    for (int i = 0; i < 4; i++) split_bf16(vals[i], h[i], l[i]);
    *(__nv_bfloat162*)&g_meanH[base]     = {h[0], h[1]};
    *(__nv_bfloat162*)&g_meanH[base + 2] = {h[2], h[3]};
    *(__nv_bfloat162*)&g_meanL[base]     = {l[0], l[1]};
    *(__nv_bfloat162*)&g_meanL[base + 2] = {l[2], l[3]};
}

// codebook split + norms for rows {2g, 2g+1}
__device__ void unit_cb(int g, const float* __restrict__ codebook)
{
    __shared__ float redc[2][4];
    int t = threadIdx.x;
    int half = t >> 7, tt = t & 127;
    int j = 2 * g + half;

    float4 v = ((const float4*)codebook)[j * 128 + tt];
    float vals[4] = {v.x, v.y, v.z, v.w};
    size_t base = (size_t)j * DD + tt * 4;
    __nv_bfloat16 h[4], l[4];
    #pragma unroll
    for (int i = 0; i < 4; i++) split_bf16(vals[i], h[i], l[i]);
    *(__nv_bfloat162*)&g_cbH[base]     = {h[0], h[1]};
    *(__nv_bfloat162*)&g_cbH[base + 2] = {h[2], h[3]};
    *(__nv_bfloat162*)&g_cbL[base]     = {l[0], l[1]};
    *(__nv_bfloat162*)&g_cbL[base + 2] = {l[2], l[3]};

    float s = v.x * v.x + v.y * v.y + v.z * v.z + v.w * v.w;
    #pragma unroll
    for (int o = 16; o > 0; o >>= 1) s += __shfl_down_sync(0xffffffffu, s, o);
    if ((tt & 31) == 0) redc[half][tt >> 5] = s;
    __syncthreads();
    if (tt == 0) g_cnorm[j] = redc[half][0] + redc[half][1] + redc[half][2] + redc[half][3];
}

// one 32x32 transpose+split tile of W [KD,ND] -> Wt [ND,KD]
__device__ void unit_wt(int w, const float* __restrict__ W,
                        __nv_bfloat16* __restrict__ WtH, __nv_bfloat16* __restrict__ WtL,
                        int KD, int ND)
{
    __shared__ float ts[32][33];
    int t = threadIdx.x;
    int nblk = ND / 32;
    int n0 = (w % nblk) * 32, k0 = (w / nblk) * 32;
    int tx = t & 31, ty = t >> 5;   // 32 x 8
    #pragma unroll
    for (int i = ty; i < 32; i += 8)
        ts[i][tx] = W[(size_t)(k0 + i) * ND + n0 + tx];
    __syncthreads();
    #pragma unroll
    for (int i = ty; i < 32; i += 8) {
        float v = ts[tx][i];
        __nv_bfloat16 h, l;
        split_bf16(v, h, l);
        size_t o = (size_t)(n0 + i) * KD + k0 + tx;
        WtH[o] = h;
        WtL[o] = l;
    }
}

// ---------------------------------------------------------------------------
// GEMM tile unit (mma.sync bf16x3, fp32 accum), identical math to R7.
// WHICH=0: hid = relu(mean @ W1t^T + b1)  BM=128
// WHICH=1: u   = hid @ W2t^T + b2         BM=64   (+ out_ue)
// WHICH=2: fused scores+argmin partials   BM=128
// ---------------------------------------------------------------------------
template<int BM, int WHICH>
__device__ void gemm_unit(int bx, int by, const float* __restrict__ bias,
                          float* __restrict__ out_ue)
{
    constexpr int BN  = 64;
    constexpr int WM  = BM / 4;
    constexpr int MT  = WM / 16;
    constexpr int STAGE = 2 * (BM + BN) * 128;

    const __nv_bfloat16 *Ah, *Al, *Bh, *Bl;
    int N, Kd;
    if (WHICH == 0) { Ah = g_meanH; Al = g_meanL; Bh = g_W1tH; Bl = g_W1tL; N = HHID; Kd = DD; }
    else if (WHICH == 1) { Ah = g_hidH; Al = g_hidL; Bh = g_W2tH; Bl = g_W2tL; N = DD; Kd = HHID; }
    else { Ah = g_uH; Al = g_uL; Bh = g_cbH; Bl = g_cbL; N = CBK; Kd = DD; }

    extern __shared__ char dsmem[];
    const uint32_t sbase = smem_u32(dsmem);
    const int tid  = threadIdx.x;
    const int lane = tid & 31;
    const int w    = tid >> 5;
    const int warp_m0 = (w >> 1) * WM;
    const int warp_n0 = (w & 1) * 32;
    const int bm = by * BM, bn = bx * BN;

    auto loadT = [&](const __nv_bfloat16* __restrict__ src, int row0, int k0,
                     uint32_t dst, int R) {
        #pragma unroll 4
        for (int i = 0; i < R * 8; i += 256) {
            int u = tid + i;
            int r = u >> 3, c8 = u & 7;
            uint32_t sd = dst + r * 128 + ((c8 * 16) ^ ((r & 7) << 4));
            const __nv_bfloat16* gs = src + (size_t)(row0 + r) * Kd + k0 + c8 * 8;
            CP_ASYNC16(sd, gs);
        }
    };
    auto issue = [&](int c, int buf) {
        uint32_t sb = sbase + (uint32_t)buf * STAGE;
        int k0 = c * 64;
        loadT(Ah, bm, k0, sb, BM);
        loadT(Al, bm, k0, sb + BM * 128, BM);
        loadT(Bh, bn, k0, sb + 2 * BM * 128, BN);
        loadT(Bl, bn, k0, sb + 2 * BM * 128 + BN * 128, BN);
    };

    const int tile = lane >> 3, lr = lane & 7;
    const uint32_t xorp = (uint32_t)(lr << 4);
    const int aRow = warp_m0 + ((tile & 1) << 3) + lr;
    const uint32_t aK = (uint32_t)((tile >> 1) << 4);
    const int bRow = warp_n0 + ((tile >> 1) << 3) + lr;
    const uint32_t bK = (uint32_t)((tile & 1) << 4);

    float acc[MT][4][4] = {};

    const int NC = Kd / 64;
    issue(0, 0); CP_COMMIT();
    issue(1, 1); CP_COMMIT();
    CP_WAIT1();
    __syncthreads();

    for (int c = 0; c < NC; c++) {
        uint32_t s0 = sbase + (uint32_t)(c & 1) * STAGE;
        uint32_t pA[2] = { s0, s0 + BM * 128 };
        uint32_t pB[2] = { s0 + 2 * BM * 128, s0 + 2 * BM * 128 + BN * 128 };

        #pragma unroll
        for (int kk = 0; kk < 4; kk++) {
            uint32_t akb = (((uint32_t)kk << 5) + aK) ^ xorp;
            uint32_t bkb = (((uint32_t)kk << 5) + bK) ^ xorp;
            uint32_t a[2][MT][4];
            uint32_t b[2][4][2];
            #pragma unroll
            for (int s = 0; s < 2; s++)
                #pragma unroll
                for (int mt = 0; mt < MT; mt++)
                    ldsm4(a[s][mt], pA[s] + (uint32_t)(aRow + mt * 16) * 128 + akb);
            #pragma unroll
            for (int s = 0; s < 2; s++)
                #pragma unroll
                for (int ng = 0; ng < 2; ng++) {
                    uint32_t t4[4];
                    ldsm4(t4, pB[s] + (uint32_t)(bRow + ng * 16) * 128 + bkb);
                    b[s][2 * ng][0] = t4[0]; b[s][2 * ng][1] = t4[1];
                    b[s][2 * ng + 1][0] = t4[2]; b[s][2 * ng + 1][1] = t4[3];
                }
            #pragma unroll
            for (int mt = 0; mt < MT; mt++)
                #pragma unroll
                for (int nt = 0; nt < 4; nt++)
                    mma16816(acc[mt][nt], a[0][mt], b[0][nt][0], b[0][nt][1]);
            #pragma unroll
            for (int mt = 0; mt < MT; mt++)
                #pragma unroll
                for (int nt = 0; nt < 4; nt++)
                    mma16816(acc[mt][nt], a[0][mt], b[1][nt][0], b[1][nt][1]);
            #pragma unroll
            for (int mt = 0; mt < MT; mt++)
                #pragma unroll
                for (int nt = 0; nt < 4; nt++)
                    mma16816(acc[mt][nt], a[1][mt], b[0][nt][0], b[0][nt][1]);
        }

        if (c == NC - 1) break;
        __syncthreads();
        if (c + 2 < NC) { issue(c + 2, c & 1); CP_COMMIT(); CP_WAIT1(); }
        else            { CP_WAIT0(); }
        __syncthreads();
    }

    const int lr4 = lane >> 2;
    const int lc2 = (lane & 3) * 2;

    if (WHICH == 2) {
        int chunk = (bn + warp_n0) >> 5;
        #pragma unroll
        for (int mt = 0; mt < MT; mt++)
            #pragma unroll
            for (int half = 0; half < 2; half++) {
                int row = bm + warp_m0 + mt * 16 + lr4 + half * 8;
                float mv = 3.0e38f; int mj = 0x7fffffff;
                #pragma unroll
                for (int nt = 0; nt < 4; nt++) {
                    int col = bn + warp_n0 + nt * 8 + lc2;
                    float2 cn = *(const float2*)&g_cnorm[col];
                    float s0 = cn.x - 2.0f * acc[mt][nt][half * 2 + 0];
                    float s1 = cn.y - 2.0f * acc[mt][nt][half * 2 + 1];
                    if (s0 < mv) { mv = s0; mj = col; }
                    if (s1 < mv) { mv = s1; mj = col + 1; }
                }
                #pragma unroll
                for (int o = 1; o < 4; o <<= 1) {
                    float ov = __shfl_xor_sync(0xffffffffu, mv, o);
                    int   oj = __shfl_xor_sync(0xffffffffu, mj, o);
                    if (ov < mv || (ov == mv && oj < mj)) { mv = ov; mj = oj; }
                }
                if ((lane & 3) == 0) {
                    g_pval[(size_t)row * NBW + chunk] = mv;
                    g_pidx[(size_t)row * NBW + chunk] = mj;
                }
            }
    } else {
        #pragma unroll
        for (int mt = 0; mt < MT; mt++)
            #pragma unroll
            for (int half = 0; half < 2; half++) {
                int row = bm + warp_m0 + mt * 16 + lr4 + half * 8;
                #pragma unroll
                for (int nt = 0; nt < 4; nt++) {
                    int col = bn + warp_n0 + nt * 8 + lc2;
                    float2 bv = *(const float2*)&bias[col];
                    float v0 = acc[mt][nt][half * 2 + 0] + bv.x;
                    float v1 = acc[mt][nt][half * 2 + 1] + bv.y;
                    size_t o = (size_t)row * N + col;
                    if (WHICH == 0) {
                        v0 = fmaxf(v0, 0.f); v1 = fmaxf(v1, 0.f);
                        __nv_bfloat16 h0, l0, h1, l1;
                        split_bf16(v0, h0, l0); split_bf16(v1, h1, l1);
                        *(__nv_bfloat162*)&g_hidH[o] = {h0, h1};
                        *(__nv_bfloat162*)&g_hidL[o] = {l0, l1};
                    } else {
                        *(float2*)&g_u[o] = make_float2(v0, v1);
                        out_ue[o] = v0; out_ue[o + 1] = v1;
                        __nv_bfloat16 h0, l0, h1, l1;
                        split_bf16(v0, h0, l0); split_bf16(v1, h1, l1);
                        *(__nv_bfloat162*)&g_uH[o] = {h0, h1};
                        *(__nv_bfloat162*)&g_uL[o] = {l0, l1};
                    }
                }
            }
    }
}

// ---------------------------------------------------------------------------
// Epilogue unit: rows {2e, 2e+1}: final argmin over 64 partials, VQ outputs,
// pos/neg gathers, diff partials; last unit does the fixed-tree diff reduce.
// ---------------------------------------------------------------------------
__device__ void unit_epi(int e, const float* __restrict__ codebook,
                         const float* __restrict__ item_embed,
                         const int* __restrict__ pos, const int* __restrict__ neg,
                         float* __restrict__ out_q, float* __restrict__ out_pos,
                         float* __restrict__ out_neg, float* __restrict__ out_diff)
{
    __shared__ float pv2[2][64];
    __shared__ int   pi2[2][64];
    __shared__ int   sid[2];
    __shared__ float rede[2][4];
    __shared__ float sv[256];
    __shared__ bool  s_last;

    int t = threadIdx.x;
    int half = t >> 7, tt = t & 127;
    int b = 2 * e + half;

    if (tt < 64) {
        pv2[half][tt] = g_pval[(size_t)b * NBW + tt];
        pi2[half][tt] = g_pidx[(size_t)b * NBW + tt];
    }
    __syncthreads();
    if (tt < 32) {
        float v1 = pv2[half][tt]; int i1 = pi2[half][tt];
        float v2 = pv2[half][tt + 32]; int i2 = pi2[half][tt + 32];
        if (v2 < v1 || (v2 == v1 && i2 < i1)) { v1 = v2; i1 = i2; }
        #pragma unroll
        for (int o = 16; o > 0; o >>= 1) {
            float ov = __shfl_down_sync(0xffffffffu, v1, o);
            int   oi = __shfl_down_sync(0xffffffffu, i1, o);
            if (ov < v1 || (ov == v1 && oi < i1)) { v1 = ov; i1 = oi; }
        }
        if (tt == 0) sid[half] = i1;
    }
    __syncthreads();
    int id = sid[half];

    float4 q = ((const float4*)codebook)[(size_t)id * 128 + tt];
    float4 u = ((const float4*)g_u)[(size_t)b * 128 + tt];
    float4 d = make_float4(q.x - u.x, q.y - u.y, q.z - u.z, q.w - u.w);
    float4 qu = make_float4(u.x + d.x, u.y + d.y, u.z + d.z, u.w + d.w);
    ((float4*)out_q)[(size_t)b * 128 + tt] = qu;

    int p = pos[b], n = neg[b];
    ((float4*)out_pos)[(size_t)b * 128 + tt] = ((const float4*)item_embed)[(size_t)p * 128 + tt];
    ((float4*)out_neg)[(size_t)b * 128 + tt] = ((const float4*)item_embed)[(size_t)n * 128 + tt];

    float ds = d.x * d.x + d.y * d.y + d.z * d.z + d.w * d.w;
    #pragma unroll
    for (int o = 16; o > 0; o >>= 1) ds += __shfl_down_sync(0xffffffffu, ds, o);
    if ((tt & 31) == 0) rede[half][tt >> 5] = ds;
    __syncthreads();
    if (tt == 0)
        g_bsum[b] = rede[half][0] + rede[half][1] + rede[half][2] + rede[half][3];
    __syncthreads();
    if (t == 0) {
        __threadfence();
        int c = atomicAdd(&g_count, 1);
        s_last = (c == BB / 2 - 1);
    }
    __syncthreads();

    if (s_last) {
        __threadfence();
        float s = 0.f;
        #pragma unroll
        for (int i = 0; i < BB / 256; i++) s += g_bsum[t + i * 256];
        sv[t] = s;
        __syncthreads();
        for (int o = 128; o > 0; o >>= 1) {
            if (t < o) sv[t] += sv[t + o];
            __syncthreads();
        }
        if (t == 0) *out_diff = sv[0] * (1.0f / (float)BD);
    }
}

// ---------------------------------------------------------------------------
// Persistent DAG megakernel. 304 CTAs x 256 threads, 5 ticket queues.
// ---------------------------------------------------------------------------
__global__ void __launch_bounds__(256, 2) mega_kernel(
    const int* __restrict__ items, const float* __restrict__ item_embed,
    const float* __restrict__ codebook,
    const float* __restrict__ W1, const float* __restrict__ b1,
    const float* __restrict__ W2, const float* __restrict__ b2,
    const int* __restrict__ pos, const int* __restrict__ neg,
    float* __restrict__ out_q, float* __restrict__ out_pos,
    float* __restrict__ out_neg, float* __restrict__ out_diff,
    float* __restrict__ out_ue)
{
    __shared__ int s_tick;
    const int t = threadIdx.x;

    // -------- Q1: W1t(512) | gather(1024) | cb(1024) | W2t(512) = 3072 --------
    for (;;) {
        if (t == 0) s_tick = atomicAdd(&t_q1, 1);
        __syncthreads();
        int u = s_tick;
        if (u >= 3072) break;
        if (u < 512) {
            unit_wt(u, W1, g_W1tH, g_W1tL, DD, HHID);
            __syncthreads();
            __threadfence();
            if (t == 0) atomicAdd(&c_w1, 1);
        } else if (u < 1536) {
            int g = u - 512;
            unit_gather(g, items, item_embed);
            __syncthreads();
            __threadfence();
            if (t == 0) atomicAdd(&c_mean[g >> 6], 1);     // 64 units per 128-row group
        } else if (u < 2560) {
            unit_cb(u - 1536, codebook);
            __syncthreads();
            __threadfence();
            if (t == 0) atomicAdd(&c_cb, 1);
        } else {
            unit_wt(u - 2560, W2, g_W2tH, g_W2tL, HHID, DD);
            __syncthreads();
            __threadfence();
            if (t == 0) atomicAdd(&c_w2, 1);
        }
        __syncthreads();
    }

    // -------- Q2: gemm0 tiles (16x, 16y) = 256 --------
    for (;;) {
        if (t == 0) s_tick = atomicAdd(&t_q2, 1);
        __syncthreads();
        int u = s_tick;
        if (u >= 256) break;
        int by = u >> 4, bx = u & 15;
        if (t == 0) { wait_ge(&c_w1, 512); wait_ge(&c_mean[by], 64); }
        __syncthreads();
        gemm_unit<128, 0>(bx, by, b1, nullptr);
        __syncthreads();
        __threadfence();
        if (t == 0) atomicAdd(&c_hid[by], 1);              // 16 x-tiles per group
        __syncthreads();
    }

    // -------- Q3: gemm1 tiles (8x, 32y) = 256 --------
    for (;;) {
        if (t == 0) s_tick = atomicAdd(&t_q3, 1);
        __syncthreads();
        int u = s_tick;
        if (u >= 256) break;
        int by = u >> 3, bx = u & 7;
        if (t == 0) { wait_ge(&c_w2, 512); wait_ge(&c_hid[by >> 1], 16); }
        __syncthreads();
        gemm_unit<64, 1>(bx, by, b2, out_ue);
        __syncthreads();
        __threadfence();
        if (t == 0) atomicAdd(&c_u[by >> 1], 1);           // 16 tiles per 128-row group
        __syncthreads();
    }

    // -------- Q4: gemm2 tiles (32x, 16y) = 512 --------
    for (;;) {
        if (t == 0) s_tick = atomicAdd(&t_q4, 1);
        __syncthreads();
        int u = s_tick;
        if (u >= 512) break;
        int by = u >> 5, bx = u & 31;
        if (t == 0) { wait_ge(&c_cb, 1024); wait_ge(&c_u[by], 16); }
        __syncthreads();
        gemm_unit<128, 2>(bx, by, nullptr, nullptr);
        __syncthreads();
        __threadfence();
        if (t == 0) atomicAdd(&c_p[by], 1);                // 32 x-tiles per group
        __syncthreads();
    }

    // -------- Q5: epilogue units (2 rows each) = 1024 --------
    for (;;) {
        if (t == 0) s_tick = atomicAdd(&t_q5, 1);
        __syncthreads();
        int u = s_tick;
        if (u >= 1024) break;
        if (t == 0) wait_ge(&c_p[u >> 6], 32);
        __syncthreads();
        unit_epi(u, codebook, item_embed, pos, neg, out_q, out_pos, out_neg, out_diff);
        __syncthreads();
    }
}

// ---------------------------------------------------------------------------
// Reset all scheduling state for the next call / graph replay.
// ---------------------------------------------------------------------------
__global__ void reset_kernel()
{
    t_q1 = 0; t_q2 = 0; t_q3 = 0; t_q4 = 0; t_q5 = 0;
    c_w1 = 0; c_w2 = 0; c_cb = 0; g_count = 0;
    #pragma unroll
    for (int i = 0; i < 16; i++) {
        c_mean[i] = 0; c_hid[i] = 0; c_u[i] = 0; c_p[i] = 0;
    }
}

// ---------------------------------------------------------------------------
extern "C" void kernel_launch(void* const* d_in, const int* in_sizes, int n_in,
                              void* d_out, int out_size)
{
    const int*   items      = (const int*)  d_in[1];
    const int*   pos        = (const int*)  d_in[2];
    const int*   neg        = (const int*)  d_in[3];
    const float* item_embed = (const float*)d_in[4];
    const float* W1         = (const float*)d_in[5];
    const float* b1         = (const float*)d_in[6];
    const float* W2         = (const float*)d_in[7];
    const float* b2         = (const float*)d_in[8];
    const float* codebook   = (const float*)d_in[9];

    float* out      = (float*)d_out;
    float* out_q    = out;
    float* out_pos  = out + (size_t)BD;
    float* out_neg  = out + (size_t)2 * BD;
    float* out_diff = out + (size_t)3 * BD;
    float* out_ue   = out + (size_t)3 * BD + 1;

    const int DSMEM = 2 * 2 * (128 + 64) * 128;   // 98304 B gemm pipeline
    cudaFuncSetAttribute(mega_kernel, cudaFuncAttributeMaxDynamicSharedMemorySize, DSMEM);

    mega_kernel<<<304, 256, DSMEM>>>(items, item_embed, codebook,
                                     W1, b1, W2, b2, pos, neg,
                                     out_q, out_pos, out_neg, out_diff, out_ue);
    reset_kernel<<<1, 1>>>();
}

// round 9
// speedup vs baseline: 1.3332x; 1.3332x over previous
#include <cuda_runtime.h>
#include <cuda_bf16.h>
#include <cstdint>

// Problem constants
#define BB    2048     // batch
#define HB    1024     // half batch
#define KHIST 200      // history length
#define DD    512      // latent dim
#define HHID  1024     // 2*D
#define CBK   2048     // codebook size
#define BD    (BB*DD)  // 1048576
#define NBW   64       // CBK / 32 argmin partial chunks per row

// ---------------- scratch (device globals; no allocation allowed) ----------
__device__ float        g_u[BB * DD];
__device__ float        g_cnorm[CBK];
__device__ float        g_pval[BB * NBW];
__device__ int          g_pidx[BB * NBW];
__device__ float        g_bsum[BB];
__device__ int          g_count;          // zero-init; self-resetting

// bf16 hi/lo split operands
__device__ __nv_bfloat16 g_meanH[BB * DD],   g_meanL[BB * DD];
__device__ __nv_bfloat16 g_hidH [BB * HHID], g_hidL [BB * HHID];
__device__ __nv_bfloat16 g_uH   [BB * DD],   g_uL   [BB * DD];
__device__ __nv_bfloat16 g_W1tH [HHID * DD], g_W1tL [HHID * DD];
__device__ __nv_bfloat16 g_W2tH [DD * HHID], g_W2tL [DD * HHID];
__device__ __nv_bfloat16 g_cbH  [CBK * DD],  g_cbL  [CBK * DD];

// ---------------------------------------------------------------------------
// Portable PTX helpers
// ---------------------------------------------------------------------------
__device__ __forceinline__ uint32_t smem_u32(const void* p) {
    uint32_t a;
    asm("{ .reg .u64 t; cvta.to.shared.u64 t, %1; cvt.u32.u64 %0, t; }" : "=r"(a) : "l"(p));
    return a;
}

#define CP_ASYNC16(dst, src) \
    asm volatile("cp.async.cg.shared.global [%0], [%1], 16;" :: "r"(dst), "l"(src))
#define CP_COMMIT() asm volatile("cp.async.commit_group;" ::: "memory")
#define CP_WAIT0()  asm volatile("cp.async.wait_group 0;" ::: "memory")
#define CP_WAIT1()  asm volatile("cp.async.wait_group 1;" ::: "memory")

__device__ __forceinline__ void ldsm4(uint32_t (&r)[4], uint32_t addr) {
    asm volatile("ldmatrix.sync.aligned.m8n8.x4.shared.b16 {%0,%1,%2,%3}, [%4];"
                 : "=r"(r[0]), "=r"(r[1]), "=r"(r[2]), "=r"(r[3]) : "r"(addr));
}

__device__ __forceinline__ void mma16816(float (&d)[4], const uint32_t (&a)[4],
                                         uint32_t b0, uint32_t b1) {
    asm volatile(
        "mma.sync.aligned.m16n8k16.row.col.f32.bf16.bf16.f32 "
        "{%0,%1,%2,%3}, {%4,%5,%6,%7}, {%8,%9}, {%0,%1,%2,%3};"
        : "+f"(d[0]), "+f"(d[1]), "+f"(d[2]), "+f"(d[3])
        : "r"(a[0]), "r"(a[1]), "r"(a[2]), "r"(a[3]), "r"(b0), "r"(b1));
}

__device__ __forceinline__ void split_bf16(float v, __nv_bfloat16& h, __nv_bfloat16& l) {
    h = __float2bfloat16(v);
    l = __float2bfloat16(v - __bfloat162float(h));
}

// ---------------------------------------------------------------------------
// Gather+mean for one half of the batch (grid = HB blocks of 128 threads).
// ---------------------------------------------------------------------------
__global__ void __launch_bounds__(128) gather_kernel(
    const int* __restrict__ items, const float* __restrict__ item_embed, int row0)
{
    int b = row0 + blockIdx.x;
    int t = threadIdx.x;
    __shared__ int sidx[KHIST];
    for (int i = t; i < KHIST; i += 128) sidx[i] = items[b * KHIST + i];
    __syncthreads();

    const float4* E4 = (const float4*)item_embed;
    float4 acc = make_float4(0.f, 0.f, 0.f, 0.f);
    int cnt = 0;
    #pragma unroll 4
    for (int k = 0; k < KHIST; k++) {
        int idx = sidx[k];
        float m = (idx != 0) ? 1.0f : 0.0f;
        cnt += (idx != 0);
        float4 v = E4[(size_t)idx * 128 + t];
        acc.x += m * v.x; acc.y += m * v.y; acc.z += m * v.z; acc.w += m * v.w;
    }
    float inv = 1.0f / (float)cnt;
    float vals[4] = {acc.x * inv, acc.y * inv, acc.z * inv, acc.w * inv};
    size_t base = (size_t)b * DD + t * 4;
    __nv_bfloat16 h[4], l[4];
    #pragma unroll
    for (int i = 0; i < 4; i++) split_bf16(vals[i], h[i], l[i]);
    *(__nv_bfloat162*)&g_meanH[base]     = {h[0], h[1]};
    *(__nv_bfloat162*)&g_meanH[base + 2] = {h[2], h[3]};
    *(__nv_bfloat162*)&g_meanL[base]     = {l[0], l[1]};
    *(__nv_bfloat162*)&g_meanL[base + 2] = {l[2], l[3]};
}

// ---------------------------------------------------------------------------
// Misc prep: codebook split+norms (2048) | W1t split (512) | W2t split (512)
// ---------------------------------------------------------------------------
__global__ void __launch_bounds__(128) misc_prep_kernel(
    const float* __restrict__ codebook,
    const float* __restrict__ W1, const float* __restrict__ W2)
{
    __shared__ float ts[32][33];
    __shared__ float red[4];
    const int blk = blockIdx.x;
    const int t = threadIdx.x;

    if (blk < 2048) {
        int j = blk;
        float4 v = ((const float4*)codebook)[j * 128 + t];
        float vals[4] = {v.x, v.y, v.z, v.w};
        size_t base = (size_t)j * DD + t * 4;
        __nv_bfloat16 h[4], l[4];
        #pragma unroll
        for (int i = 0; i < 4; i++) split_bf16(vals[i], h[i], l[i]);
        *(__nv_bfloat162*)&g_cbH[base]     = {h[0], h[1]};
        *(__nv_bfloat162*)&g_cbH[base + 2] = {h[2], h[3]};
        *(__nv_bfloat162*)&g_cbL[base]     = {l[0], l[1]};
        *(__nv_bfloat162*)&g_cbL[base + 2] = {l[2], l[3]};

        float s = v.x * v.x + v.y * v.y + v.z * v.z + v.w * v.w;
        #pragma unroll
        for (int o = 16; o > 0; o >>= 1) s += __shfl_down_sync(0xffffffffu, s, o);
        if ((t & 31) == 0) red[t >> 5] = s;
        __syncthreads();
        if (t == 0) g_cnorm[j] = red[0] + red[1] + red[2] + red[3];
    } else {
        const float* W;
        __nv_bfloat16 *WtH, *WtL;
        int KD, ND, w;
        if (blk < 2560) {
            w = blk - 2048; W = W1; WtH = g_W1tH; WtL = g_W1tL; KD = DD; ND = HHID;
        } else {
            w = blk - 2560; W = W2; WtH = g_W2tH; WtL = g_W2tL; KD = HHID; ND = DD;
        }
        int nblk = ND / 32;
        int n0 = (w % nblk) * 32, k0 = (w / nblk) * 32;
        int tx = t & 31, ty = t >> 5;
        #pragma unroll
        for (int i = ty; i < 32; i += 4)
            ts[i][tx] = W[(size_t)(k0 + i) * ND + n0 + tx];
        __syncthreads();
        #pragma unroll
        for (int i = ty; i < 32; i += 4) {
            float v = ts[tx][i];
            __nv_bfloat16 h, l;
            split_bf16(v, h, l);
            size_t o = (size_t)(n0 + i) * KD + k0 + tx;
            WtH[o] = h;
            WtL[o] = l;
        }
    }
}

// ---------------------------------------------------------------------------
// Tensor-core GEMM (mma.sync bf16x3, fp32 accum): C = A[M,Kd] @ B[N,Kd]^T
// Identical math to R7; row0 selects the batch half.
// WHICH=0: hid = relu(mean @ W1t^T + b1)  BM=128
// WHICH=1: u   = hid @ W2t^T + b2         BM=64   (+ out_ue)
// WHICH=2: fused scores+argmin partials   BM=128
// ---------------------------------------------------------------------------
template<int BM, int WHICH>
__global__ void __launch_bounds__(256, (BM == 64) ? 3 : 2) gemm_mma(
    const __nv_bfloat16* __restrict__ Ah, const __nv_bfloat16* __restrict__ Al,
    const __nv_bfloat16* __restrict__ Bh, const __nv_bfloat16* __restrict__ Bl,
    const float* __restrict__ bias, float* __restrict__ out_ue,
    int N, int Kd, int row0)
{
    constexpr int BN  = 64;
    constexpr int WM  = BM / 4;
    constexpr int MT  = WM / 16;
    constexpr int STAGE = 2 * (BM + BN) * 128;

    extern __shared__ char smem[];
    const uint32_t sbase = smem_u32(smem);
    const int tid  = threadIdx.x;
    const int lane = tid & 31;
    const int w    = tid >> 5;
    const int warp_m0 = (w >> 1) * WM;
    const int warp_n0 = (w & 1) * 32;
    const int bm = row0 + blockIdx.y * BM, bn = blockIdx.x * BN;

    auto loadT = [&](const __nv_bfloat16* __restrict__ src, int r0, int k0,
                     uint32_t dst, int R) {
        #pragma unroll 4
        for (int i = 0; i < R * 8; i += 256) {
            int u = tid + i;
            int r = u >> 3, c8 = u & 7;
            uint32_t sd = dst + r * 128 + ((c8 * 16) ^ ((r & 7) << 4));
            const __nv_bfloat16* gs = src + (size_t)(r0 + r) * Kd + k0 + c8 * 8;
            CP_ASYNC16(sd, gs);
        }
    };
    auto issue = [&](int c, int buf) {
        uint32_t sb = sbase + (uint32_t)buf * STAGE;
        int k0 = c * 64;
        loadT(Ah, bm, k0, sb, BM);
        loadT(Al, bm, k0, sb + BM * 128, BM);
        loadT(Bh, bn, k0, sb + 2 * BM * 128, BN);
        loadT(Bl, bn, k0, sb + 2 * BM * 128 + BN * 128, BN);
    };

    const int tile = lane >> 3, lr = lane & 7;
    const uint32_t xorp = (uint32_t)(lr << 4);
    const int aRow = warp_m0 + ((tile & 1) << 3) + lr;
    const uint32_t aK = (uint32_t)((tile >> 1) << 4);
    const int bRow = warp_n0 + ((tile >> 1) << 3) + lr;
    const uint32_t bK = (uint32_t)((tile & 1) << 4);

    float acc[MT][4][4] = {};

    const int NC = Kd / 64;
    issue(0, 0); CP_COMMIT();
    issue(1, 1); CP_COMMIT();
    CP_WAIT1();
    __syncthreads();

    for (int c = 0; c < NC; c++) {
        uint32_t s0 = sbase + (uint32_t)(c & 1) * STAGE;
        uint32_t pA[2] = { s0, s0 + BM * 128 };
        uint32_t pB[2] = { s0 + 2 * BM * 128, s0 + 2 * BM * 128 + BN * 128 };

        #pragma unroll
        for (int kk = 0; kk < 4; kk++) {
            uint32_t akb = (((uint32_t)kk << 5) + aK) ^ xorp;
            uint32_t bkb = (((uint32_t)kk << 5) + bK) ^ xorp;
            uint32_t a[2][MT][4];
            uint32_t b[2][4][2];
            #pragma unroll
            for (int s = 0; s < 2; s++)
                #pragma unroll
                for (int mt = 0; mt < MT; mt++)
                    ldsm4(a[s][mt], pA[s] + (uint32_t)(aRow + mt * 16) * 128 + akb);
            #pragma unroll
            for (int s = 0; s < 2; s++)
                #pragma unroll
                for (int ng = 0; ng < 2; ng++) {
                    uint32_t t4[4];
                    ldsm4(t4, pB[s] + (uint32_t)(bRow + ng * 16) * 128 + bkb);
                    b[s][2 * ng][0] = t4[0]; b[s][2 * ng][1] = t4[1];
                    b[s][2 * ng + 1][0] = t4[2]; b[s][2 * ng + 1][1] = t4[3];
                }
            #pragma unroll
            for (int mt = 0; mt < MT; mt++)
                #pragma unroll
                for (int nt = 0; nt < 4; nt++)
                    mma16816(acc[mt][nt], a[0][mt], b[0][nt][0], b[0][nt][1]);
            #pragma unroll
            for (int mt = 0; mt < MT; mt++)
                #pragma unroll
                for (int nt = 0; nt < 4; nt++)
                    mma16816(acc[mt][nt], a[0][mt], b[1][nt][0], b[1][nt][1]);
            #pragma unroll
            for (int mt = 0; mt < MT; mt++)
                #pragma unroll
                for (int nt = 0; nt < 4; nt++)
                    mma16816(acc[mt][nt], a[1][mt], b[0][nt][0], b[0][nt][1]);
        }

        if (c == NC - 1) break;
        __syncthreads();
        if (c + 2 < NC) { issue(c + 2, c & 1); CP_COMMIT(); CP_WAIT1(); }
        else            { CP_WAIT0(); }
        __syncthreads();
    }

    const int lr4 = lane >> 2;
    const int lc2 = (lane & 3) * 2;

    if (WHICH == 2) {
        int chunk = (bn + warp_n0) >> 5;
        #pragma unroll
        for (int mt = 0; mt < MT; mt++)
            #pragma unroll
            for (int half = 0; half < 2; half++) {
                int row = bm + warp_m0 + mt * 16 + lr4 + half * 8;
                float mv = 3.0e38f; int mj = 0x7fffffff;
                #pragma unroll
                for (int nt = 0; nt < 4; nt++) {
                    int col = bn + warp_n0 + nt * 8 + lc2;
                    float2 cn = *(const float2*)&g_cnorm[col];
                    float s0 = cn.x - 2.0f * acc[mt][nt][half * 2 + 0];
                    float s1 = cn.y - 2.0f * acc[mt][nt][half * 2 + 1];
                    if (s0 < mv) { mv = s0; mj = col; }
                    if (s1 < mv) { mv = s1; mj = col + 1; }
                }
                #pragma unroll
                for (int o = 1; o < 4; o <<= 1) {
                    float ov = __shfl_xor_sync(0xffffffffu, mv, o);
                    int   oj = __shfl_xor_sync(0xffffffffu, mj, o);
                    if (ov < mv || (ov == mv && oj < mj)) { mv = ov; mj = oj; }
                }
                if ((lane & 3) == 0) {
                    g_pval[(size_t)row * NBW + chunk] = mv;
                    g_pidx[(size_t)row * NBW + chunk] = mj;
                }
            }
    } else {
        #pragma unroll
        for (int mt = 0; mt < MT; mt++)
            #pragma unroll
            for (int half = 0; half < 2; half++) {
                int row = bm + warp_m0 + mt * 16 + lr4 + half * 8;
                #pragma unroll
                for (int nt = 0; nt < 4; nt++) {
                    int col = bn + warp_n0 + nt * 8 + lc2;
                    float2 bv = *(const float2*)&bias[col];
                    float v0 = acc[mt][nt][half * 2 + 0] + bv.x;
                    float v1 = acc[mt][nt][half * 2 + 1] + bv.y;
                    size_t o = (size_t)row * N + col;
                    if (WHICH == 0) {
                        v0 = fmaxf(v0, 0.f); v1 = fmaxf(v1, 0.f);
                        __nv_bfloat16 h0, l0, h1, l1;
                        split_bf16(v0, h0, l0); split_bf16(v1, h1, l1);
                        *(__nv_bfloat162*)&g_hidH[o] = {h0, h1};
                        *(__nv_bfloat162*)&g_hidL[o] = {l0, l1};
                    } else {
                        *(float2*)&g_u[o] = make_float2(v0, v1);
                        out_ue[o] = v0; out_ue[o + 1] = v1;
                        __nv_bfloat16 h0, l0, h1, l1;
                        split_bf16(v0, h0, l0); split_bf16(v1, h1, l1);
                        *(__nv_bfloat162*)&g_uH[o] = {h0, h1};
                        *(__nv_bfloat162*)&g_uL[o] = {l0, l1};
                    }
                }
            }
    }
}

// ---------------------------------------------------------------------------
// Epilogue for one half (grid = HB): final argmin over 64 partials, VQ
// outputs, pos/neg gathers, diff partials; very last block (across both
// halves/streams) does the fixed-tree diff reduction and resets the counter.
// ---------------------------------------------------------------------------
__global__ void __launch_bounds__(128) epilogue_kernel(
    const float* __restrict__ codebook, const float* __restrict__ item_embed,
    const int* __restrict__ pos, const int* __restrict__ neg,
    float* __restrict__ out_q, float* __restrict__ out_pos,
    float* __restrict__ out_neg, float* __restrict__ out_diff, int row0)
{
    int b = row0 + blockIdx.x;
    int t = threadIdx.x;

    __shared__ float pv[64];
    __shared__ int   pi[64];
    __shared__ int   s_id;
    __shared__ bool  s_last;
    if (t < 64) {
        pv[t] = g_pval[(size_t)b * NBW + t];
        pi[t] = g_pidx[(size_t)b * NBW + t];
    }
    __syncthreads();
    if (t < 32) {
        float v1 = pv[t]; int i1 = pi[t];
        float v2 = pv[t + 32]; int i2 = pi[t + 32];
        if (v2 < v1 || (v2 == v1 && i2 < i1)) { v1 = v2; i1 = i2; }
        #pragma unroll
        for (int o = 16; o > 0; o >>= 1) {
            float ov = __shfl_down_sync(0xffffffffu, v1, o);
            int   oi = __shfl_down_sync(0xffffffffu, i1, o);
            if (ov < v1 || (ov == v1 && oi < i1)) { v1 = ov; i1 = oi; }
        }
        if (t == 0) s_id = i1;
    }
    __syncthreads();
    int id = s_id;

    float4 q = ((const float4*)codebook)[(size_t)id * 128 + t];
    float4 u = ((const float4*)g_u)[(size_t)b * 128 + t];
    float4 d = make_float4(q.x - u.x, q.y - u.y, q.z - u.z, q.w - u.w);
    float4 qu = make_float4(u.x + d.x, u.y + d.y, u.z + d.z, u.w + d.w);
    ((float4*)out_q)[(size_t)b * 128 + t] = qu;

    int p = pos[b], n = neg[b];
    ((float4*)out_pos)[(size_t)b * 128 + t] = ((const float4*)item_embed)[(size_t)p * 128 + t];
    ((float4*)out_neg)[(size_t)b * 128 + t] = ((const float4*)item_embed)[(size_t)n * 128 + t];

    float ds = d.x * d.x + d.y * d.y + d.z * d.z + d.w * d.w;
    #pragma unroll
    for (int o = 16; o > 0; o >>= 1) ds += __shfl_down_sync(0xffffffffu, ds, o);
    __shared__ float red[4];
    if ((t & 31) == 0) red[t >> 5] = ds;
    __syncthreads();
    if (t == 0) {
        g_bsum[b] = red[0] + red[1] + red[2] + red[3];
        __threadfence();
        int c = atomicAdd(&g_count, 1);
        s_last = (c == BB - 1);
    }
    __syncthreads();

    if (s_last) {
        __threadfence();
        float s = 0.f;
        #pragma unroll
        for (int i = 0; i < BB / 128; i++) s += g_bsum[t + i * 128];
        __shared__ float sv[128];
        sv[t] = s;
        __syncthreads();
        for (int o = 64; o > 0; o >>= 1) {
            if (t < o) sv[t] += sv[t + o];
            __syncthreads();
        }
        if (t == 0) {
            *out_diff = sv[0] * (1.0f / (float)BD);
            g_count = 0;                       // reset for next graph replay
        }
    }
}

// ---------------------------------------------------------------------------
extern "C" void kernel_launch(void* const* d_in, const int* in_sizes, int n_in,
                              void* d_out, int out_size)
{
    const int*   items      = (const int*)  d_in[1];
    const int*   pos        = (const int*)  d_in[2];
    const int*   neg        = (const int*)  d_in[3];
    const float* item_embed = (const float*)d_in[4];
    const float* W1         = (const float*)d_in[5];
    const float* b1         = (const float*)d_in[6];
    const float* W2         = (const float*)d_in[7];
    const float* b2         = (const float*)d_in[8];
    const float* codebook   = (const float*)d_in[9];

    float* out      = (float*)d_out;
    float* out_q    = out;
    float* out_pos  = out + (size_t)BD;
    float* out_neg  = out + (size_t)2 * BD;
    float* out_diff = out + (size_t)3 * BD;
    float* out_ue   = out + (size_t)3 * BD + 1;

    const int SMEM_128 = 2 * 2 * (128 + 64) * 128;  // 98304
    const int SMEM_64  = 2 * 2 * (64 + 64) * 128;   // 65536

    // One-time setup on the first (uncaptured, correctness) call.
    static cudaStream_t s1 = nullptr;
    static cudaEvent_t evFork = nullptr, evMisc = nullptr, evG0 = nullptr, evEnd1 = nullptr;
    if (s1 == nullptr) {
        cudaFuncSetAttribute((const void*)gemm_mma<128, 0>,
                             cudaFuncAttributeMaxDynamicSharedMemorySize, SMEM_128);
        cudaFuncSetAttribute((const void*)gemm_mma<64, 1>,
                             cudaFuncAttributeMaxDynamicSharedMemorySize, SMEM_64);
        cudaFuncSetAttribute((const void*)gemm_mma<128, 2>,
                             cudaFuncAttributeMaxDynamicSharedMemorySize, SMEM_128);
        cudaStreamCreateWithFlags(&s1, cudaStreamNonBlocking);
        cudaEventCreateWithFlags(&evFork, cudaEventDisableTiming);
        cudaEventCreateWithFlags(&evMisc, cudaEventDisableTiming);
        cudaEventCreateWithFlags(&evG0,   cudaEventDisableTiming);
        cudaEventCreateWithFlags(&evEnd1, cudaEventDisableTiming);
    }

    __nv_bfloat16 *meanH, *meanL, *hidH, *hidL, *uH, *uL, *w1tH, *w1tL, *w2tH, *w2tL, *cbH, *cbL;
    cudaGetSymbolAddress((void**)&meanH, g_meanH);
    cudaGetSymbolAddress((void**)&meanL, g_meanL);
    cudaGetSymbolAddress((void**)&hidH,  g_hidH);
    cudaGetSymbolAddress((void**)&hidL,  g_hidL);
    cudaGetSymbolAddress((void**)&uH,    g_uH);
    cudaGetSymbolAddress((void**)&uL,    g_uL);
    cudaGetSymbolAddress((void**)&w1tH,  g_W1tH);
    cudaGetSymbolAddress((void**)&w1tL,  g_W1tL);
    cudaGetSymbolAddress((void**)&w2tH,  g_W2tH);
    cudaGetSymbolAddress((void**)&w2tL,  g_W2tL);
    cudaGetSymbolAddress((void**)&cbH,   g_cbH);
    cudaGetSymbolAddress((void**)&cbL,   g_cbL);

    // ---- fork: s1 runs misc prep concurrently with gather(h0) on stream 0 ----
    cudaEventRecord(evFork, 0);
    cudaStreamWaitEvent(s1, evFork, 0);
    misc_prep_kernel<<<3072, 128, 0, s1>>>(codebook, W1, W2);
    cudaEventRecord(evMisc, s1);

    gather_kernel<<<HB, 128>>>(items, item_embed, 0);        // stream 0: half 0
    cudaEventRecord(evG0, 0);
    cudaStreamWaitEvent(s1, evG0, 0);

    // ---- s1: half-0 GEMM chain + epilogue (overlaps gather(h1) on stream 0) --
    gemm_mma<128, 0><<<dim3(HHID / 64, HB / 128), 256, SMEM_128, s1>>>(
        meanH, meanL, w1tH, w1tL, b1, nullptr, HHID, DD, 0);
    gemm_mma<64, 1><<<dim3(DD / 64, HB / 64), 256, SMEM_64, s1>>>(
        hidH,  hidL,  w2tH, w2tL, b2, out_ue,  DD,  HHID, 0);
    gemm_mma<128, 2><<<dim3(CBK / 64, HB / 128), 256, SMEM_128, s1>>>(
        uH,    uL,    cbH,  cbL,  nullptr, nullptr, CBK, DD, 0);
    epilogue_kernel<<<HB, 128, 0, s1>>>(codebook, item_embed, pos, neg,
                                        out_q, out_pos, out_neg, out_diff, 0);
    cudaEventRecord(evEnd1, s1);

    // ---- stream 0: gather(h1), then half-1 chain ----
    gather_kernel<<<HB, 128>>>(items, item_embed, HB);
    cudaStreamWaitEvent(0, evMisc, 0);   // W/cb splits ready before gemm0(h1)
    gemm_mma<128, 0><<<dim3(HHID / 64, HB / 128), 256, SMEM_128>>>(
        meanH, meanL, w1tH, w1tL, b1, nullptr, HHID, DD, HB);
    gemm_mma<64, 1><<<dim3(DD / 64, HB / 64), 256, SMEM_64>>>(
        hidH,  hidL,  w2tH, w2tL, b2, out_ue,  DD,  HHID, HB);
    gemm_mma<128, 2><<<dim3(CBK / 64, HB / 128), 256, SMEM_128>>>(
        uH,    uL,    cbH,  cbL,  nullptr, nullptr, CBK, DD, HB);
    epilogue_kernel<<<HB, 128>>>(codebook, item_embed, pos, neg,
                                 out_q, out_pos, out_neg, out_diff, HB);

    // ---- join s1 back into stream 0 ----
    cudaStreamWaitEvent(0, evEnd1, 0);
}